// round 1
// baseline (speedup 1.0000x reference)
#include <cuda_runtime.h>
#include <math.h>

#define F_LEN 1000.0f
#define IMG   512.0f
#define EPSF  1e-8f
#define EPSD  1e-8

// accumulators: 0 shape, 1 pose, 2 betas, 3 n_valid, 4 kp2d, 5 kp3d, 6 pa
__device__ double g_acc[7];

__global__ void init_kernel() {
    if (threadIdx.x < 7) g_acc[threadIdx.x] = 0.0;
}

// ---------------------------------------------------------------------------
// Vertex loss: sum over b,v,c of mask[b] * |pred - gt|
// ---------------------------------------------------------------------------
__global__ void vert_kernel(const float* __restrict__ pv,
                            const float* __restrict__ gv,
                            const int*   __restrict__ has_smpl,
                            int n4, int ntot, int per_batch)
{
    __shared__ double sh[32];
    const float4* pv4 = reinterpret_cast<const float4*>(pv);
    const float4* gv4 = reinterpret_cast<const float4*>(gv);

    float local = 0.0f;
    for (int i = blockIdx.x * blockDim.x + threadIdx.x; i < n4;
         i += gridDim.x * blockDim.x) {
        float4 a = __ldg(pv4 + i);
        float4 b = __ldg(gv4 + i);
        int e  = i * 4;
        int b0 = e / per_batch;
        int r  = e - b0 * per_batch;
        float d0 = fabsf(a.x - b.x);
        float d1 = fabsf(a.y - b.y);
        float d2 = fabsf(a.z - b.z);
        float d3 = fabsf(a.w - b.w);
        if (r + 3 < per_batch) {
            float m = (__ldg(has_smpl + b0) > 0) ? 1.0f : 0.0f;
            local += m * (d0 + d1 + d2 + d3);
        } else {
            float d[4] = {d0, d1, d2, d3};
            #pragma unroll
            for (int k = 0; k < 4; k++) {
                int bb = (e + k) / per_batch;
                float m = (__ldg(has_smpl + bb) > 0) ? 1.0f : 0.0f;
                local += m * d[k];
            }
        }
    }
    // scalar tail (if total not divisible by 4)
    if (blockIdx.x == 0 && threadIdx.x == 0) {
        for (int e = n4 * 4; e < ntot; ++e) {
            int bb = e / per_batch;
            float m = (__ldg(has_smpl + bb) > 0) ? 1.0f : 0.0f;
            local += m * fabsf(__ldg(pv + e) - __ldg(gv + e));
        }
    }

    // block reduction -> one double atomic per block
    double v = (double)local;
    #pragma unroll
    for (int o = 16; o; o >>= 1) v += __shfl_down_sync(0xffffffffu, v, o);
    int lane = threadIdx.x & 31, wid = threadIdx.x >> 5;
    if (lane == 0) sh[wid] = v;
    __syncthreads();
    if (wid == 0) {
        int nw = blockDim.x >> 5;
        v = (lane < nw) ? sh[lane] : 0.0;
        #pragma unroll
        for (int o = 16; o; o >>= 1) v += __shfl_down_sync(0xffffffffu, v, o);
        if (lane == 0) atomicAdd(&g_acc[0], v);
    }
}

// ---------------------------------------------------------------------------
// 3x3 symmetric Jacobi eigensolver (double)
// ---------------------------------------------------------------------------
__device__ void jacobi3(double A[3][3], double V[3][3])
{
    #pragma unroll
    for (int r = 0; r < 3; r++)
        #pragma unroll
        for (int c = 0; c < 3; c++) V[r][c] = (r == c) ? 1.0 : 0.0;

    for (int sweep = 0; sweep < 25; ++sweep) {
        double off = A[0][1]*A[0][1] + A[0][2]*A[0][2] + A[1][2]*A[1][2];
        if (off < 1e-26) break;
        #pragma unroll
        for (int p = 0; p < 2; p++) {
            #pragma unroll
            for (int q = p + 1; q < 3; q++) {
                double apq = A[p][q];
                if (fabs(apq) < 1e-300) continue;
                double theta = (A[q][q] - A[p][p]) / (2.0 * apq);
                double t = 1.0 / (fabs(theta) + sqrt(theta*theta + 1.0));
                if (theta < 0.0) t = -t;
                double c = 1.0 / sqrt(t*t + 1.0);
                double s = t * c;
                double app = A[p][p], aqq = A[q][q];
                A[p][p] = app - t * apq;
                A[q][q] = aqq + t * apq;
                A[p][q] = A[q][p] = 0.0;
                int k = 3 - p - q;   // the remaining index
                double akp = A[k][p], akq = A[k][q];
                A[k][p] = A[p][k] = c * akp - s * akq;
                A[k][q] = A[q][k] = s * akp + c * akq;
                #pragma unroll
                for (int r = 0; r < 3; r++) {
                    double vrp = V[r][p], vrq = V[r][q];
                    V[r][p] = c * vrp - s * vrq;
                    V[r][q] = s * vrp + c * vrq;
                }
            }
        }
    }
}

// ---------------------------------------------------------------------------
// Per-batch losses + Procrustes (one thread per batch element)
// ---------------------------------------------------------------------------
__global__ void batch_kernel(const float* __restrict__ pred_rotmat,
                             const float* __restrict__ pred_camera,
                             const float* __restrict__ pred_joints,
                             const float* __restrict__ pred_betas,
                             const float* __restrict__ gt_rotmat,
                             const float* __restrict__ gt_shape,
                             const float* __restrict__ gt_kp2d,
                             const float* __restrict__ gt_kp3d,
                             const int*   __restrict__ has_smpl,
                             int B)
{
    const int J = 24;
    int b = blockIdx.x * blockDim.x + threadIdx.x;

    double a_kp2d = 0.0, a_kp3d = 0.0, a_pose = 0.0, a_betas = 0.0;
    double a_nv = 0.0, a_pa = 0.0;

    if (b < B) {
        float p[24][3], g[24][3], c3[24];
        for (int j = 0; j < J; j++) {
            p[j][0] = __ldg(pred_joints + (b*J + j)*3 + 0);
            p[j][1] = __ldg(pred_joints + (b*J + j)*3 + 1);
            p[j][2] = __ldg(pred_joints + (b*J + j)*3 + 2);
            g[j][0] = __ldg(gt_kp3d + (b*J + j)*4 + 0);
            g[j][1] = __ldg(gt_kp3d + (b*J + j)*4 + 1);
            g[j][2] = __ldg(gt_kp3d + (b*J + j)*4 + 2);
            c3[j]   = __ldg(gt_kp3d + (b*J + j)*4 + 3);
        }

        // ---- kp2d ----
        float cam0 = __ldg(pred_camera + b*3 + 0);
        float cam1 = __ldg(pred_camera + b*3 + 1);
        float cam2 = __ldg(pred_camera + b*3 + 2);
        float depth = 2.0f * F_LEN / (EPSF + cam0 * IMG);
        float skp2 = 0.0f;
        for (int j = 0; j < J; j++) {
            float pz = p[j][2] + depth;
            float kx = (F_LEN * (p[j][0] + cam1) / pz + IMG * 0.5f) / IMG;
            float ky = (F_LEN * (p[j][1] + cam2) / pz + IMG * 0.5f) / IMG;
            float gx = __ldg(gt_kp2d + (b*J + j)*3 + 0) / IMG;
            float gy = __ldg(gt_kp2d + (b*J + j)*3 + 1) / IMG;
            float cf = __ldg(gt_kp2d + (b*J + j)*3 + 2);
            skp2 += cf * (fabsf(kx - gx) + fabsf(ky - gy));
        }
        a_kp2d = (double)skp2;

        // ---- kp3d (pelvis-centered) ----
        float pp[3], gp[3];
        for (int a = 0; a < 3; a++) {
            pp[a] = 0.5f * (p[2][a] + p[3][a]);
            gp[a] = 0.5f * (g[2][a] + g[3][a]);
        }
        float sk3 = 0.0f;
        for (int j = 0; j < J; j++)
            for (int a = 0; a < 3; a++)
                sk3 += c3[j] * fabsf((p[j][a] - pp[a]) - (g[j][a] - gp[a]));
        a_kp3d = (double)sk3;

        // ---- masked pose / betas / n_valid ----
        float m = (__ldg(has_smpl + b) > 0) ? 1.0f : 0.0f;
        a_nv = (double)m;
        float sp = 0.0f;
        for (int i = 0; i < 216; i++) {
            float d = __ldg(pred_rotmat + b*216 + i) - __ldg(gt_rotmat + b*216 + i);
            sp += d * d;
        }
        a_pose = (double)(m * sp);
        float sb = 0.0f;
        for (int i = 0; i < 10; i++) {
            float d = __ldg(pred_betas + b*10 + i) - __ldg(gt_shape + b*10 + i);
            sb += d * d;
        }
        a_betas = (double)(m * sb);

        // ---- Procrustes (double precision) ----
        double mu1[3] = {0,0,0}, mu2[3] = {0,0,0};
        for (int j = 0; j < J; j++)
            for (int a = 0; a < 3; a++) {
                mu1[a] += (double)p[j][a];
                mu2[a] += (double)g[j][a];
            }
        for (int a = 0; a < 3; a++) { mu1[a] /= J; mu2[a] /= J; }

        double K[3][3];
        for (int r = 0; r < 3; r++)
            for (int c = 0; c < 3; c++) K[r][c] = EPSD;  // reference adds EPS elementwise
        double var1 = 0.0;
        for (int j = 0; j < J; j++) {
            double x1[3], x2[3];
            for (int a = 0; a < 3; a++) {
                x1[a] = (double)p[j][a] - mu1[a];
                x2[a] = (double)g[j][a] - mu2[a];
                var1 += x1[a] * x1[a];
            }
            for (int r = 0; r < 3; r++)
                for (int c = 0; c < 3; c++)
                    K[r][c] += x1[r] * x2[c];
        }

        // A = K^T K
        double A[3][3];
        for (int r = 0; r < 3; r++)
            for (int c = 0; c < 3; c++) {
                double s = 0.0;
                for (int k = 0; k < 3; k++) s += K[k][r] * K[k][c];
                A[r][c] = s;
            }
        double Vv[3][3];
        jacobi3(A, Vv);
        double w[3] = {A[0][0], A[1][1], A[2][2]};
        // sort eigenpairs descending
        for (int i = 0; i < 2; i++) {
            int mx = i;
            for (int j2 = i + 1; j2 < 3; j2++) if (w[j2] > w[mx]) mx = j2;
            if (mx != i) {
                double tw = w[i]; w[i] = w[mx]; w[mx] = tw;
                for (int r = 0; r < 3; r++) {
                    double tv = Vv[r][i]; Vv[r][i] = Vv[r][mx]; Vv[r][mx] = tv;
                }
            }
        }
        double sv[3];
        for (int i = 0; i < 3; i++) sv[i] = sqrt(fmax(w[i], 0.0));

        double detK = K[0][0]*(K[1][1]*K[2][2] - K[1][2]*K[2][1])
                    - K[0][1]*(K[1][0]*K[2][2] - K[1][2]*K[2][0])
                    + K[0][2]*(K[1][0]*K[2][1] - K[1][1]*K[2][0]);
        double sgn = (detK > 0.0) ? 1.0 : ((detK < 0.0) ? -1.0 : 0.0);
        double z[3] = {1.0, 1.0, sgn};

        // R = sum_i (z_i / s_i) * v_i * (K v_i)^T
        double R[3][3] = {{0,0,0},{0,0,0},{0,0,0}};
        for (int i = 0; i < 3; i++) {
            double kv[3];
            for (int r = 0; r < 3; r++)
                kv[r] = K[r][0]*Vv[0][i] + K[r][1]*Vv[1][i] + K[r][2]*Vv[2][i];
            double f = z[i] / fmax(sv[i], 1e-30);
            for (int r = 0; r < 3; r++)
                for (int c = 0; c < 3; c++)
                    R[r][c] += f * Vv[r][i] * kv[c];
        }
        double trRK = 0.0;
        for (int r = 0; r < 3; r++)
            for (int c = 0; c < 3; c++) trRK += R[r][c] * K[c][r];
        double scale = trRK / var1;

        double t[3];
        for (int r = 0; r < 3; r++)
            t[r] = mu2[r] - scale * (R[r][0]*mu1[0] + R[r][1]*mu1[1] + R[r][2]*mu1[2]);

        double errsum = 0.0;
        for (int j = 0; j < J; j++) {
            double h[3];
            for (int r = 0; r < 3; r++)
                h[r] = scale * (R[r][0]*(double)p[j][0] + R[r][1]*(double)p[j][1]
                              + R[r][2]*(double)p[j][2]) + t[r] - (double)g[j][r];
            errsum += sqrt(h[0]*h[0] + h[1]*h[1] + h[2]*h[2]);
        }
        a_pa = errsum;
    }

    // warp reduce + lane-0 atomic per accumulator
    unsigned mask_full = 0xffffffffu;
    #pragma unroll
    for (int o = 16; o; o >>= 1) {
        a_kp2d  += __shfl_down_sync(mask_full, a_kp2d,  o);
        a_kp3d  += __shfl_down_sync(mask_full, a_kp3d,  o);
        a_pose  += __shfl_down_sync(mask_full, a_pose,  o);
        a_betas += __shfl_down_sync(mask_full, a_betas, o);
        a_nv    += __shfl_down_sync(mask_full, a_nv,    o);
        a_pa    += __shfl_down_sync(mask_full, a_pa,    o);
    }
    if ((threadIdx.x & 31) == 0) {
        atomicAdd(&g_acc[4], a_kp2d);
        atomicAdd(&g_acc[5], a_kp3d);
        atomicAdd(&g_acc[1], a_pose);
        atomicAdd(&g_acc[2], a_betas);
        atomicAdd(&g_acc[3], a_nv);
        atomicAdd(&g_acc[6], a_pa);
    }
}

// ---------------------------------------------------------------------------
__global__ void finalize_kernel(float* out, int B, int V)
{
    double nv         = g_acc[3];
    double loss_shape = g_acc[0] / (nv * (double)V * 3.0 + EPSD);
    double loss_pose  = g_acc[1] / (nv * 24.0 * 9.0 + EPSD);
    double loss_betas = g_acc[2] / (nv * 10.0 + EPSD);
    double l2 = g_acc[4] / ((double)B * 24.0 * 2.0);
    double l3 = g_acc[5] / ((double)B * 24.0 * 3.0);
    double pa = g_acc[6] / ((double)B * 24.0);
    out[0] = (float)(4.0*l2 + 4.0*l3 + loss_shape + loss_pose + 0.01*loss_betas + pa);
}

// ---------------------------------------------------------------------------
extern "C" void kernel_launch(void* const* d_in, const int* in_sizes, int n_in,
                              void* d_out, int out_size)
{
    const float* pred_rotmat   = (const float*)d_in[0];
    const float* pred_camera   = (const float*)d_in[1];
    const float* pred_joints   = (const float*)d_in[2];
    const float* pred_vertices = (const float*)d_in[3];
    const float* pred_betas    = (const float*)d_in[4];
    const float* gt_rotmat     = (const float*)d_in[5];
    const float* gt_shape      = (const float*)d_in[6];
    const float* gt_kp2d       = (const float*)d_in[7];
    const float* gt_kp3d       = (const float*)d_in[8];
    const float* gt_vertices   = (const float*)d_in[9];
    const int*   has_smpl      = (const int*)d_in[10];

    int B = in_sizes[1] / 3;                 // pred_camera (B,3)
    int ntot = in_sizes[3];                  // pred_vertices total elements
    int per_batch = ntot / B;                // V*3
    int V = per_batch / 3;
    int n4 = ntot / 4;

    init_kernel<<<1, 32>>>();
    vert_kernel<<<1184, 256>>>(pred_vertices, gt_vertices, has_smpl,
                               n4, ntot, per_batch);
    int bblocks = (B + 255) / 256;
    batch_kernel<<<bblocks, 256>>>(pred_rotmat, pred_camera, pred_joints,
                                   pred_betas, gt_rotmat, gt_shape,
                                   gt_kp2d, gt_kp3d, has_smpl, B);
    finalize_kernel<<<1, 1>>>((float*)d_out, B, V);
}

// round 2
// speedup vs baseline: 8.9783x; 8.9783x over previous
#include <cuda_runtime.h>
#include <math.h>

#define F_LEN 1000.0f
#define IMG   512.0f
#define EPSF  1e-8f
#define EPSD  1e-8

// acc slots: 0 shape, 1 pose, 2 betas, 3 n_valid, 4 kp2d, 5 kp3d, 6 pa
__device__ struct {
    double acc[7];
    unsigned int done;
    unsigned int pad;
} g_state;

__device__ __forceinline__ float wsum(float v) {
    #pragma unroll
    for (int o = 16; o; o >>= 1) v += __shfl_xor_sync(0xffffffffu, v, o);
    return v;
}

// ---------------------------------------------------------------------------
// Vertex loss: sum_b,v,c mask[b] * |pred - gt|   (HBM-bound, ~85 MB)
// ---------------------------------------------------------------------------
__global__ void vert_kernel(const float* __restrict__ pv,
                            const float* __restrict__ gv,
                            const int*   __restrict__ has_smpl,
                            int n4, int ntot, int per_batch)
{
    __shared__ double sh[32];
    const float4* pv4 = reinterpret_cast<const float4*>(pv);
    const float4* gv4 = reinterpret_cast<const float4*>(gv);

    float local = 0.0f;
    for (int i = blockIdx.x * blockDim.x + threadIdx.x; i < n4;
         i += gridDim.x * blockDim.x) {
        float4 a = __ldg(pv4 + i);
        float4 b = __ldg(gv4 + i);
        int e  = i * 4;
        int b0 = e / per_batch;
        int r  = e - b0 * per_batch;
        float d0 = fabsf(a.x - b.x);
        float d1 = fabsf(a.y - b.y);
        float d2 = fabsf(a.z - b.z);
        float d3 = fabsf(a.w - b.w);
        if (r + 3 < per_batch) {
            float m = (__ldg(has_smpl + b0) > 0) ? 1.0f : 0.0f;
            local += m * (d0 + d1 + d2 + d3);
        } else {
            float d[4] = {d0, d1, d2, d3};
            #pragma unroll
            for (int k = 0; k < 4; k++) {
                int bb = (e + k) / per_batch;
                float m = (__ldg(has_smpl + bb) > 0) ? 1.0f : 0.0f;
                local += m * d[k];
            }
        }
    }
    if (blockIdx.x == 0 && threadIdx.x == 0) {
        for (int e = n4 * 4; e < ntot; ++e) {
            int bb = e / per_batch;
            float m = (__ldg(has_smpl + bb) > 0) ? 1.0f : 0.0f;
            local += m * fabsf(__ldg(pv + e) - __ldg(gv + e));
        }
    }

    double v = (double)local;
    #pragma unroll
    for (int o = 16; o; o >>= 1) v += __shfl_down_sync(0xffffffffu, v, o);
    int lane = threadIdx.x & 31, wid = threadIdx.x >> 5;
    if (lane == 0) sh[wid] = v;
    __syncthreads();
    if (wid == 0) {
        int nw = blockDim.x >> 5;
        v = (lane < nw) ? sh[lane] : 0.0;
        #pragma unroll
        for (int o = 16; o; o >>= 1) v += __shfl_down_sync(0xffffffffu, v, o);
        if (lane == 0) atomicAdd(&g_state.acc[0], v);
    }
}

// ---------------------------------------------------------------------------
// One warp per batch element: all small losses + Procrustes (fp32 Jacobi,
// redundantly on all lanes -> uniform branches, no broadcast needed).
// Last block finalizes the scalar output.
// ---------------------------------------------------------------------------
__global__ void batch_kernel(const float* __restrict__ pred_rotmat,
                             const float* __restrict__ pred_camera,
                             const float* __restrict__ pred_joints,
                             const float* __restrict__ pred_betas,
                             const float* __restrict__ gt_rotmat,
                             const float* __restrict__ gt_shape,
                             const float* __restrict__ gt_kp2d,
                             const float* __restrict__ gt_kp3d,
                             const int*   __restrict__ has_smpl,
                             int B, int V, float* __restrict__ out)
{
    const unsigned FM = 0xffffffffu;
    int gw   = (blockIdx.x * blockDim.x + threadIdx.x) >> 5;
    int lane = threadIdx.x & 31;

    if (gw < B) {
        const int b = gw;
        const bool act = (lane < 24);

        float px = 0.f, py = 0.f, pz = 0.f;
        float gx = 0.f, gy = 0.f, gz = 0.f, c3 = 0.f;
        float g2x = 0.f, g2y = 0.f, c2 = 0.f;
        if (act) {
            const float* pj = pred_joints + ((size_t)b * 24 + lane) * 3;
            px = __ldg(pj + 0); py = __ldg(pj + 1); pz = __ldg(pj + 2);
            const float* gk = gt_kp3d + ((size_t)b * 24 + lane) * 4;
            gx = __ldg(gk + 0); gy = __ldg(gk + 1); gz = __ldg(gk + 2); c3 = __ldg(gk + 3);
            const float* g2 = gt_kp2d + ((size_t)b * 24 + lane) * 3;
            g2x = __ldg(g2 + 0); g2y = __ldg(g2 + 1); c2 = __ldg(g2 + 2);
        }
        float cam0 = __ldg(pred_camera + b * 3 + 0);
        float cam1 = __ldg(pred_camera + b * 3 + 1);
        float cam2 = __ldg(pred_camera + b * 3 + 2);

        // ---- kp2d ----
        float s2 = 0.f;
        {
            float depth = 2.0f * F_LEN / (EPSF + cam0 * IMG);
            if (act) {
                float zz = pz + depth;
                float kx = (F_LEN * (px + cam1) / zz + IMG * 0.5f) * (1.0f / IMG);
                float ky = (F_LEN * (py + cam2) / zz + IMG * 0.5f) * (1.0f / IMG);
                s2 = c2 * (fabsf(kx - g2x * (1.0f / IMG)) +
                           fabsf(ky - g2y * (1.0f / IMG)));
            }
        }
        s2 = wsum(s2);

        // ---- kp3d (pelvis-centered) ----
        float ppx = 0.5f * (__shfl_sync(FM, px, 2) + __shfl_sync(FM, px, 3));
        float ppy = 0.5f * (__shfl_sync(FM, py, 2) + __shfl_sync(FM, py, 3));
        float ppz = 0.5f * (__shfl_sync(FM, pz, 2) + __shfl_sync(FM, pz, 3));
        float gpx = 0.5f * (__shfl_sync(FM, gx, 2) + __shfl_sync(FM, gx, 3));
        float gpy = 0.5f * (__shfl_sync(FM, gy, 2) + __shfl_sync(FM, gy, 3));
        float gpz = 0.5f * (__shfl_sync(FM, gz, 2) + __shfl_sync(FM, gz, 3));
        float s3 = 0.f;
        if (act) {
            s3 = c3 * (fabsf((px - ppx) - (gx - gpx)) +
                       fabsf((py - ppy) - (gy - gpy)) +
                       fabsf((pz - ppz) - (gz - gpz)));
        }
        s3 = wsum(s3);

        // ---- masked pose / betas ----
        float m = (__ldg(has_smpl + b) > 0) ? 1.0f : 0.0f;
        float sp = 0.f;
        {
            const float* pr = pred_rotmat + (size_t)b * 216;
            const float* gr = gt_rotmat   + (size_t)b * 216;
            for (int i = lane; i < 216; i += 32) {
                float d = __ldg(pr + i) - __ldg(gr + i);
                sp += d * d;
            }
        }
        sp = wsum(sp) * m;
        float sb = 0.f;
        if (lane < 10) {
            float d = __ldg(pred_betas + b * 10 + lane) - __ldg(gt_shape + b * 10 + lane);
            sb = d * d;
        }
        sb = wsum(sb) * m;

        // ---- Procrustes (fp32, per-warp) ----
        const float inv24 = 1.0f / 24.0f;
        float m1x = wsum(px) * inv24, m1y = wsum(py) * inv24, m1z = wsum(pz) * inv24;
        float m2x = wsum(gx) * inv24, m2y = wsum(gy) * inv24, m2z = wsum(gz) * inv24;

        float x1x = 0.f, x1y = 0.f, x1z = 0.f, x2x = 0.f, x2y = 0.f, x2z = 0.f;
        if (act) {
            x1x = px - m1x; x1y = py - m1y; x1z = pz - m1z;
            x2x = gx - m2x; x2y = gy - m2y; x2z = gz - m2z;
        }
        float var1 = wsum(x1x * x1x + x1y * x1y + x1z * x1z);

        float K[3][3];
        K[0][0] = wsum(x1x * x2x) + EPSF; K[0][1] = wsum(x1x * x2y) + EPSF; K[0][2] = wsum(x1x * x2z) + EPSF;
        K[1][0] = wsum(x1y * x2x) + EPSF; K[1][1] = wsum(x1y * x2y) + EPSF; K[1][2] = wsum(x1y * x2z) + EPSF;
        K[2][0] = wsum(x1z * x2x) + EPSF; K[2][1] = wsum(x1z * x2y) + EPSF; K[2][2] = wsum(x1z * x2z) + EPSF;

        // A = K^T K (symmetric PSD). Jacobi eigensolve, fp32, all lanes
        // redundantly (identical data -> identical results -> uniform branches).
        float A[3][3];
        #pragma unroll
        for (int r = 0; r < 3; r++)
            #pragma unroll
            for (int c = 0; c < 3; c++)
                A[r][c] = K[0][r] * K[0][c] + K[1][r] * K[1][c] + K[2][r] * K[2][c];

        float Vv[3][3] = {{1.f,0.f,0.f},{0.f,1.f,0.f},{0.f,0.f,1.f}};
        float nrm = A[0][0]*A[0][0] + A[1][1]*A[1][1] + A[2][2]*A[2][2];
        for (int sweep = 0; sweep < 12; ++sweep) {
            float off = A[0][1]*A[0][1] + A[0][2]*A[0][2] + A[1][2]*A[1][2];
            if (off <= 1e-14f * nrm) break;
            #pragma unroll
            for (int p = 0; p < 2; p++) {
                #pragma unroll
                for (int q = p + 1; q < 3; q++) {
                    float apq = A[p][q];
                    if (fabsf(apq) < 1e-30f) continue;
                    float theta = (A[q][q] - A[p][p]) / (2.0f * apq);
                    float t = 1.0f / (fabsf(theta) + sqrtf(theta * theta + 1.0f));
                    if (theta < 0.0f) t = -t;
                    float c = rsqrtf(t * t + 1.0f);
                    float s = t * c;
                    float app = A[p][p], aqq = A[q][q];
                    A[p][p] = app - t * apq;
                    A[q][q] = aqq + t * apq;
                    A[p][q] = A[q][p] = 0.0f;
                    int k = 3 - p - q;
                    float akp = A[k][p], akq = A[k][q];
                    A[k][p] = A[p][k] = c * akp - s * akq;
                    A[k][q] = A[q][k] = s * akp + c * akq;
                    #pragma unroll
                    for (int r = 0; r < 3; r++) {
                        float vrp = Vv[r][p], vrq = Vv[r][q];
                        Vv[r][p] = c * vrp - s * vrq;
                        Vv[r][q] = s * vrp + c * vrq;
                    }
                }
            }
        }
        float w[3] = {A[0][0], A[1][1], A[2][2]};
        #pragma unroll
        for (int i = 0; i < 2; i++) {
            int mx = i;
            #pragma unroll
            for (int j2 = 1; j2 < 3; j2++) if (j2 > i && w[j2] > w[mx]) mx = j2;
            if (mx != i) {
                float tw = w[i]; w[i] = w[mx]; w[mx] = tw;
                #pragma unroll
                for (int r = 0; r < 3; r++) {
                    float tv = Vv[r][i]; Vv[r][i] = Vv[r][mx]; Vv[r][mx] = tv;
                }
            }
        }
        float sv0 = sqrtf(fmaxf(w[0], 0.f));
        float sv1 = sqrtf(fmaxf(w[1], 0.f));
        float sv2 = sqrtf(fmaxf(w[2], 0.f));

        float detK = K[0][0]*(K[1][1]*K[2][2] - K[1][2]*K[2][1])
                   - K[0][1]*(K[1][0]*K[2][2] - K[1][2]*K[2][0])
                   + K[0][2]*(K[1][0]*K[2][1] - K[1][1]*K[2][0]);
        float sgn = (detK > 0.f) ? 1.f : ((detK < 0.f) ? -1.f : 0.f);
        float z[3] = {1.f, 1.f, sgn};
        float sv[3] = {sv0, sv1, sv2};

        // R = sum_i (z_i / s_i) * v_i * (K v_i)^T
        float R[3][3] = {{0,0,0},{0,0,0},{0,0,0}};
        #pragma unroll
        for (int i = 0; i < 3; i++) {
            float kv[3];
            #pragma unroll
            for (int r = 0; r < 3; r++)
                kv[r] = K[r][0]*Vv[0][i] + K[r][1]*Vv[1][i] + K[r][2]*Vv[2][i];
            float f = z[i] / fmaxf(sv[i], 1e-30f);
            #pragma unroll
            for (int r = 0; r < 3; r++)
                #pragma unroll
                for (int c = 0; c < 3; c++)
                    R[r][c] += f * Vv[r][i] * kv[c];
        }
        float trRK = 0.f;
        #pragma unroll
        for (int r = 0; r < 3; r++)
            #pragma unroll
            for (int c = 0; c < 3; c++) trRK += R[r][c] * K[c][r];
        float scale = trRK / var1;

        float tx = m2x - scale * (R[0][0]*m1x + R[0][1]*m1y + R[0][2]*m1z);
        float ty = m2y - scale * (R[1][0]*m1x + R[1][1]*m1y + R[1][2]*m1z);
        float tz = m2z - scale * (R[2][0]*m1x + R[2][1]*m1y + R[2][2]*m1z);

        float err = 0.f;
        if (act) {
            float hx = scale * (R[0][0]*px + R[0][1]*py + R[0][2]*pz) + tx - gx;
            float hy = scale * (R[1][0]*px + R[1][1]*py + R[1][2]*pz) + ty - gy;
            float hz = scale * (R[2][0]*px + R[2][1]*py + R[2][2]*pz) + tz - gz;
            err = sqrtf(hx*hx + hy*hy + hz*hz);
        }
        err = wsum(err);

        if (lane == 0) {
            atomicAdd(&g_state.acc[4], (double)s2);
            atomicAdd(&g_state.acc[5], (double)s3);
            atomicAdd(&g_state.acc[1], (double)sp);
            atomicAdd(&g_state.acc[2], (double)sb);
            atomicAdd(&g_state.acc[3], (double)m);
            atomicAdd(&g_state.acc[6], (double)err);
        }
    }

    // ---- last block finalizes (vert_kernel already complete: stream order) ----
    __syncthreads();
    __threadfence();
    if (threadIdx.x == 0) {
        unsigned old = atomicInc(&g_state.done, gridDim.x - 1);
        if (old == gridDim.x - 1) {
            __threadfence();
            volatile double* a = g_state.acc;
            double nv         = a[3];
            double loss_shape = a[0] / (nv * (double)V * 3.0 + EPSD);
            double loss_pose  = a[1] / (nv * 216.0 + EPSD);
            double loss_betas = a[2] / (nv * 10.0 + EPSD);
            double l2 = a[4] / ((double)B * 48.0);
            double l3 = a[5] / ((double)B * 72.0);
            double pa = a[6] / ((double)B * 24.0);
            out[0] = (float)(4.0*l2 + 4.0*l3 + loss_shape + loss_pose
                             + 0.01*loss_betas + pa);
        }
    }
}

// ---------------------------------------------------------------------------
extern "C" void kernel_launch(void* const* d_in, const int* in_sizes, int n_in,
                              void* d_out, int out_size)
{
    const float* pred_rotmat   = (const float*)d_in[0];
    const float* pred_camera   = (const float*)d_in[1];
    const float* pred_joints   = (const float*)d_in[2];
    const float* pred_vertices = (const float*)d_in[3];
    const float* pred_betas    = (const float*)d_in[4];
    const float* gt_rotmat     = (const float*)d_in[5];
    const float* gt_shape      = (const float*)d_in[6];
    const float* gt_kp2d       = (const float*)d_in[7];
    const float* gt_kp3d       = (const float*)d_in[8];
    const float* gt_vertices   = (const float*)d_in[9];
    const int*   has_smpl      = (const int*)d_in[10];

    int B = in_sizes[1] / 3;
    int ntot = in_sizes[3];
    int per_batch = ntot / B;
    int V = per_batch / 3;
    int n4 = ntot / 4;

    void* statePtr = nullptr;
    cudaGetSymbolAddress(&statePtr, g_state);
    cudaMemsetAsync(statePtr, 0, sizeof(g_state));

    vert_kernel<<<1184, 256>>>(pred_vertices, gt_vertices, has_smpl,
                               n4, ntot, per_batch);

    int bblocks = (B * 32 + 255) / 256;
    batch_kernel<<<bblocks, 256>>>(pred_rotmat, pred_camera, pred_joints,
                                   pred_betas, gt_rotmat, gt_shape,
                                   gt_kp2d, gt_kp3d, has_smpl,
                                   B, V, (float*)d_out);
}

// round 3
// speedup vs baseline: 10.7739x; 1.2000x over previous
#include <cuda_runtime.h>
#include <math.h>

#define F_LEN 1000.0f
#define IMG   512.0f
#define EPSF  1e-8f
#define EPSD  1e-8

// acc slots: 0 shape, 1 pose, 2 betas, 3 n_valid, 4 kp23(combined), 6 pa
__device__ struct {
    double acc[7];
    unsigned int done;
    unsigned int pad;
} g_state;

__device__ __forceinline__ float wsum(float v) {
    #pragma unroll
    for (int o = 16; o; o >>= 1) v += __shfl_xor_sync(0xffffffffu, v, o);
    return v;
}

// ---------------------------------------------------------------------------
// Block-level reduce of one float into a global double slot
// ---------------------------------------------------------------------------
__device__ __forceinline__ void block_reduce_add(float local, double* slot,
                                                 double* sh)
{
    double v = (double)local;
    #pragma unroll
    for (int o = 16; o; o >>= 1) v += __shfl_down_sync(0xffffffffu, v, o);
    int lane = threadIdx.x & 31, wid = threadIdx.x >> 5;
    if (lane == 0) sh[wid] = v;
    __syncthreads();
    if (wid == 0) {
        int nw = blockDim.x >> 5;
        v = (lane < nw) ? sh[lane] : 0.0;
        #pragma unroll
        for (int o = 16; o; o >>= 1) v += __shfl_down_sync(0xffffffffu, v, o);
        if (lane == 0) atomicAdd(slot, v);
    }
    __syncthreads();
}

// ---------------------------------------------------------------------------
// Fused kernel.
//   blocks [0, batchBlocks)            : per-batch losses + Procrustes (warp/batch)
//   blocks [batchBlocks, gridDim.x)    : vertex L1 + pose L2 (grid-stride, HBM)
//   last block to finish               : finalize scalar output
// ---------------------------------------------------------------------------
__global__ void fused_kernel(const float* __restrict__ pred_rotmat,
                             const float* __restrict__ pred_camera,
                             const float* __restrict__ pred_joints,
                             const float* __restrict__ pred_vertices,
                             const float* __restrict__ pred_betas,
                             const float* __restrict__ gt_rotmat,
                             const float* __restrict__ gt_shape,
                             const float* __restrict__ gt_kp2d,
                             const float* __restrict__ gt_kp3d,
                             const float* __restrict__ gt_vertices,
                             const int*   __restrict__ has_smpl,
                             int B, int V, int batchBlocks,
                             float* __restrict__ out)
{
    __shared__ double sh[32];
    const unsigned FM = 0xffffffffu;
    const int per_batch = V * 3;
    const int ntot = B * per_batch;
    const int n4 = ntot / 4;

    if (blockIdx.x >= batchBlocks) {
        // ================= vertex + pose (memory-bound) =================
        const int vblocks = gridDim.x - batchBlocks;
        const int vbid = blockIdx.x - batchBlocks;
        const float4* pv4 = reinterpret_cast<const float4*>(pred_vertices);
        const float4* gv4 = reinterpret_cast<const float4*>(gt_vertices);

        float lshape = 0.0f;
        for (int i = vbid * blockDim.x + threadIdx.x; i < n4;
             i += vblocks * blockDim.x) {
            float4 a = __ldg(pv4 + i);
            float4 b = __ldg(gv4 + i);
            int e  = i * 4;
            int b0 = e / per_batch;
            int r  = e - b0 * per_batch;
            float d0 = fabsf(a.x - b.x);
            float d1 = fabsf(a.y - b.y);
            float d2 = fabsf(a.z - b.z);
            float d3 = fabsf(a.w - b.w);
            if (r + 3 < per_batch) {
                float m = (__ldg(has_smpl + b0) > 0) ? 1.0f : 0.0f;
                lshape += m * (d0 + d1 + d2 + d3);
            } else {
                float d[4] = {d0, d1, d2, d3};
                #pragma unroll
                for (int k = 0; k < 4; k++) {
                    int bb = (e + k) / per_batch;
                    float m = (__ldg(has_smpl + bb) > 0) ? 1.0f : 0.0f;
                    lshape += m * d[k];
                }
            }
        }
        if (vbid == 0 && threadIdx.x == 0) {
            for (int e = n4 * 4; e < ntot; ++e) {
                int bb = e / per_batch;
                float m = (__ldg(has_smpl + bb) > 0) ? 1.0f : 0.0f;
                lshape += m * fabsf(__ldg(pred_vertices + e) - __ldg(gt_vertices + e));
            }
        }

        // pose loss: 216 floats per batch, 216 % 4 == 0 -> no f4 crossing
        float lpose = 0.0f;
        {
            const float4* pr4 = reinterpret_cast<const float4*>(pred_rotmat);
            const float4* gr4 = reinterpret_cast<const float4*>(gt_rotmat);
            int n4p = B * 54;   // 216/4
            for (int i = vbid * blockDim.x + threadIdx.x; i < n4p;
                 i += vblocks * blockDim.x) {
                int b0 = i / 54;
                float m = (__ldg(has_smpl + b0) > 0) ? 1.0f : 0.0f;
                float4 a = __ldg(pr4 + i);
                float4 b = __ldg(gr4 + i);
                float d0 = a.x - b.x, d1 = a.y - b.y, d2 = a.z - b.z, d3 = a.w - b.w;
                lpose += m * (d0*d0 + d1*d1 + d2*d2 + d3*d3);
            }
        }

        block_reduce_add(lshape, &g_state.acc[0], sh);
        block_reduce_add(lpose,  &g_state.acc[1], sh);
    } else {
        // ================= per-batch losses (warp per batch) =================
        int gw   = (blockIdx.x * blockDim.x + threadIdx.x) >> 5;
        int lane = threadIdx.x & 31;

        if (gw < B) {
            const int b = gw;
            const bool act = (lane < 24);

            float px = 0.f, py = 0.f, pz = 0.f;
            float gx = 0.f, gy = 0.f, gz = 0.f, c3 = 0.f;
            float g2x = 0.f, g2y = 0.f, c2 = 0.f;
            if (act) {
                const float* pj = pred_joints + ((size_t)b * 24 + lane) * 3;
                px = __ldg(pj + 0); py = __ldg(pj + 1); pz = __ldg(pj + 2);
                const float* gk = gt_kp3d + ((size_t)b * 24 + lane) * 4;
                gx = __ldg(gk + 0); gy = __ldg(gk + 1); gz = __ldg(gk + 2); c3 = __ldg(gk + 3);
                const float* g2 = gt_kp2d + ((size_t)b * 24 + lane) * 3;
                g2x = __ldg(g2 + 0); g2y = __ldg(g2 + 1); c2 = __ldg(g2 + 2);
            }
            float cam0 = __ldg(pred_camera + b * 3 + 0);
            float cam1 = __ldg(pred_camera + b * 3 + 1);
            float cam2 = __ldg(pred_camera + b * 3 + 2);

            // ---- kp2d ----
            float s2 = 0.f;
            {
                float depth = __fdividef(2.0f * F_LEN, EPSF + cam0 * IMG);
                if (act) {
                    float invz = __fdividef(1.0f, pz + depth);
                    float kx = (F_LEN * (px + cam1) * invz + IMG * 0.5f) * (1.0f / IMG);
                    float ky = (F_LEN * (py + cam2) * invz + IMG * 0.5f) * (1.0f / IMG);
                    s2 = c2 * (fabsf(kx - g2x * (1.0f / IMG)) +
                               fabsf(ky - g2y * (1.0f / IMG)));
                }
            }

            // ---- kp3d (pelvis-centered) ----
            float ppx = 0.5f * (__shfl_sync(FM, px, 2) + __shfl_sync(FM, px, 3));
            float ppy = 0.5f * (__shfl_sync(FM, py, 2) + __shfl_sync(FM, py, 3));
            float ppz = 0.5f * (__shfl_sync(FM, pz, 2) + __shfl_sync(FM, pz, 3));
            float gpx = 0.5f * (__shfl_sync(FM, gx, 2) + __shfl_sync(FM, gx, 3));
            float gpy = 0.5f * (__shfl_sync(FM, gy, 2) + __shfl_sync(FM, gy, 3));
            float gpz = 0.5f * (__shfl_sync(FM, gz, 2) + __shfl_sync(FM, gz, 3));
            float s3 = 0.f;
            if (act) {
                s3 = c3 * (fabsf((px - ppx) - (gx - gpx)) +
                           fabsf((py - ppy) - (gy - gpy)) +
                           fabsf((pz - ppz) - (gz - gpz)));
            }
            // combined, pre-weighted: total term = 4*(S2/(B*48) + S3/(B*72))
            float s23 = wsum(s2 * (1.0f / 48.0f) + s3 * (1.0f / 72.0f));

            // ---- masked betas ----
            float m = (__ldg(has_smpl + b) > 0) ? 1.0f : 0.0f;
            float sb = 0.f;
            if (lane < 10) {
                float d = __ldg(pred_betas + b * 10 + lane) - __ldg(gt_shape + b * 10 + lane);
                sb = d * d;
            }
            sb = wsum(sb) * m;

            // ---- Procrustes (fp32, per-warp, fast-math intrinsics) ----
            const float inv24 = 1.0f / 24.0f;
            float m1x = wsum(px) * inv24, m1y = wsum(py) * inv24, m1z = wsum(pz) * inv24;
            float m2x = wsum(gx) * inv24, m2y = wsum(gy) * inv24, m2z = wsum(gz) * inv24;

            float x1x = 0.f, x1y = 0.f, x1z = 0.f, x2x = 0.f, x2y = 0.f, x2z = 0.f;
            if (act) {
                x1x = px - m1x; x1y = py - m1y; x1z = pz - m1z;
                x2x = gx - m2x; x2y = gy - m2y; x2z = gz - m2z;
            }
            float var1 = wsum(x1x * x1x + x1y * x1y + x1z * x1z);

            float K[3][3];
            K[0][0] = wsum(x1x * x2x) + EPSF; K[0][1] = wsum(x1x * x2y) + EPSF; K[0][2] = wsum(x1x * x2z) + EPSF;
            K[1][0] = wsum(x1y * x2x) + EPSF; K[1][1] = wsum(x1y * x2y) + EPSF; K[1][2] = wsum(x1y * x2z) + EPSF;
            K[2][0] = wsum(x1z * x2x) + EPSF; K[2][1] = wsum(x1z * x2y) + EPSF; K[2][2] = wsum(x1z * x2z) + EPSF;

            // A = K^T K, Jacobi eigensolve (all lanes redundantly, uniform)
            float A[3][3];
            #pragma unroll
            for (int r = 0; r < 3; r++)
                #pragma unroll
                for (int c = 0; c < 3; c++)
                    A[r][c] = K[0][r] * K[0][c] + K[1][r] * K[1][c] + K[2][r] * K[2][c];

            float Vv[3][3] = {{1.f,0.f,0.f},{0.f,1.f,0.f},{0.f,0.f,1.f}};
            float nrm = A[0][0]*A[0][0] + A[1][1]*A[1][1] + A[2][2]*A[2][2];
            for (int sweep = 0; sweep < 10; ++sweep) {
                float off = A[0][1]*A[0][1] + A[0][2]*A[0][2] + A[1][2]*A[1][2];
                if (off <= 1e-14f * nrm) break;
                #pragma unroll
                for (int p = 0; p < 2; p++) {
                    #pragma unroll
                    for (int q = p + 1; q < 3; q++) {
                        float apq = A[p][q];
                        if (fabsf(apq) < 1e-30f) continue;
                        float theta = __fdividef(A[q][q] - A[p][p], 2.0f * apq);
                        float w1 = theta * theta + 1.0f;
                        float sq = w1 * rsqrtf(w1);          // sqrt(theta^2+1)
                        float t = __fdividef(1.0f, fabsf(theta) + sq);
                        if (theta < 0.0f) t = -t;
                        float c = rsqrtf(t * t + 1.0f);
                        float s = t * c;
                        float app = A[p][p], aqq = A[q][q];
                        A[p][p] = app - t * apq;
                        A[q][q] = aqq + t * apq;
                        A[p][q] = A[q][p] = 0.0f;
                        int k = 3 - p - q;
                        float akp = A[k][p], akq = A[k][q];
                        A[k][p] = A[p][k] = c * akp - s * akq;
                        A[k][q] = A[q][k] = s * akp + c * akq;
                        #pragma unroll
                        for (int r = 0; r < 3; r++) {
                            float vrp = Vv[r][p], vrq = Vv[r][q];
                            Vv[r][p] = c * vrp - s * vrq;
                            Vv[r][q] = s * vrp + c * vrq;
                        }
                    }
                }
            }
            float w[3] = {A[0][0], A[1][1], A[2][2]};
            #pragma unroll
            for (int i = 0; i < 2; i++) {
                int mx = i;
                #pragma unroll
                for (int j2 = 1; j2 < 3; j2++) if (j2 > i && w[j2] > w[mx]) mx = j2;
                if (mx != i) {
                    float tw = w[i]; w[i] = w[mx]; w[mx] = tw;
                    #pragma unroll
                    for (int r = 0; r < 3; r++) {
                        float tv = Vv[r][i]; Vv[r][i] = Vv[r][mx]; Vv[r][mx] = tv;
                    }
                }
            }

            float detK = K[0][0]*(K[1][1]*K[2][2] - K[1][2]*K[2][1])
                       - K[0][1]*(K[1][0]*K[2][2] - K[1][2]*K[2][0])
                       + K[0][2]*(K[1][0]*K[2][1] - K[1][1]*K[2][0]);
            float sgn = (detK > 0.f) ? 1.f : ((detK < 0.f) ? -1.f : 0.f);
            float z[3] = {1.f, 1.f, sgn};

            // R = sum_i (z_i / s_i) * v_i * (K v_i)^T,  1/s_i = rsqrt(lambda_i)
            float R[3][3] = {{0,0,0},{0,0,0},{0,0,0}};
            #pragma unroll
            for (int i = 0; i < 3; i++) {
                float kv[3];
                #pragma unroll
                for (int r = 0; r < 3; r++)
                    kv[r] = K[r][0]*Vv[0][i] + K[r][1]*Vv[1][i] + K[r][2]*Vv[2][i];
                float f = z[i] * rsqrtf(fmaxf(w[i], 1e-30f));
                #pragma unroll
                for (int r = 0; r < 3; r++)
                    #pragma unroll
                    for (int c = 0; c < 3; c++)
                        R[r][c] += f * Vv[r][i] * kv[c];
            }
            float trRK = 0.f;
            #pragma unroll
            for (int r = 0; r < 3; r++)
                #pragma unroll
                for (int c = 0; c < 3; c++) trRK += R[r][c] * K[c][r];
            float scale = __fdividef(trRK, var1);

            float tx = m2x - scale * (R[0][0]*m1x + R[0][1]*m1y + R[0][2]*m1z);
            float ty = m2y - scale * (R[1][0]*m1x + R[1][1]*m1y + R[1][2]*m1z);
            float tz = m2z - scale * (R[2][0]*m1x + R[2][1]*m1y + R[2][2]*m1z);

            float err = 0.f;
            if (act) {
                float hx = scale * (R[0][0]*px + R[0][1]*py + R[0][2]*pz) + tx - gx;
                float hy = scale * (R[1][0]*px + R[1][1]*py + R[1][2]*pz) + ty - gy;
                float hz = scale * (R[2][0]*px + R[2][1]*py + R[2][2]*pz) + tz - gz;
                float hsq = hx*hx + hy*hy + hz*hz;
                err = (hsq > 0.f) ? hsq * rsqrtf(hsq) : 0.f;
            }
            err = wsum(err);

            if (lane == 0) {
                atomicAdd(&g_state.acc[4], (double)s23);
                atomicAdd(&g_state.acc[2], (double)sb);
                atomicAdd(&g_state.acc[3], (double)m);
                atomicAdd(&g_state.acc[6], (double)err);
            }
        }
        __syncthreads();
    }

    // ================= finalize: last block of the whole grid =================
    __threadfence();
    if (threadIdx.x == 0) {
        unsigned old = atomicInc(&g_state.done, gridDim.x - 1);
        if (old == gridDim.x - 1) {
            __threadfence();
            volatile double* a = g_state.acc;
            double nv         = a[3];
            double loss_shape = a[0] / (nv * (double)V * 3.0 + EPSD);
            double loss_pose  = a[1] / (nv * 216.0 + EPSD);
            double loss_betas = a[2] / (nv * 10.0 + EPSD);
            double l23 = 4.0 * a[4] / (double)B;   // already pre-weighted
            double pa  = a[6] / ((double)B * 24.0);
            out[0] = (float)(l23 + loss_shape + loss_pose + 0.01*loss_betas + pa);
        }
    }
}

// ---------------------------------------------------------------------------
extern "C" void kernel_launch(void* const* d_in, const int* in_sizes, int n_in,
                              void* d_out, int out_size)
{
    const float* pred_rotmat   = (const float*)d_in[0];
    const float* pred_camera   = (const float*)d_in[1];
    const float* pred_joints   = (const float*)d_in[2];
    const float* pred_vertices = (const float*)d_in[3];
    const float* pred_betas    = (const float*)d_in[4];
    const float* gt_rotmat     = (const float*)d_in[5];
    const float* gt_shape      = (const float*)d_in[6];
    const float* gt_kp2d       = (const float*)d_in[7];
    const float* gt_kp3d       = (const float*)d_in[8];
    const float* gt_vertices   = (const float*)d_in[9];
    const int*   has_smpl      = (const int*)d_in[10];

    int B = in_sizes[1] / 3;
    int ntot = in_sizes[3];
    int V = ntot / (B * 3);

    void* statePtr = nullptr;
    cudaGetSymbolAddress(&statePtr, g_state);
    cudaMemsetAsync(statePtr, 0, sizeof(g_state));

    int batchBlocks = (B * 32 + 255) / 256;     // 64 for B=512
    int vertBlocks  = 528;
    int grid = batchBlocks + vertBlocks;

    fused_kernel<<<grid, 256>>>(pred_rotmat, pred_camera, pred_joints,
                                pred_vertices, pred_betas, gt_rotmat,
                                gt_shape, gt_kp2d, gt_kp3d, gt_vertices,
                                has_smpl, B, V, batchBlocks, (float*)d_out);
}

// round 4
// speedup vs baseline: 12.4107x; 1.1519x over previous
#include <cuda_runtime.h>
#include <math.h>

#define F_LEN 1000.0f
#define IMG   512.0f
#define EPSF  1e-8f
#define EPSD  1e-8

// acc slots: 0 shape, 1 pose, 2 betas, 3 n_valid, 4 kp23(combined), 6 pa
// Zero-initialized at module load; the finalize block re-zeroes it after use,
// so no memset is needed between graph replays.
__device__ struct {
    double acc[7];
    unsigned int done;
    unsigned int pad;
} g_state;   // static zero init

__device__ __forceinline__ float wsum(float v) {
    #pragma unroll
    for (int o = 16; o; o >>= 1) v += __shfl_xor_sync(0xffffffffu, v, o);
    return v;
}

__device__ __forceinline__ void block_reduce_add(float local, double* slot,
                                                 double* sh)
{
    double v = (double)local;
    #pragma unroll
    for (int o = 16; o; o >>= 1) v += __shfl_down_sync(0xffffffffu, v, o);
    int lane = threadIdx.x & 31, wid = threadIdx.x >> 5;
    if (lane == 0) sh[wid] = v;
    __syncthreads();
    if (wid == 0) {
        int nw = blockDim.x >> 5;
        v = (lane < nw) ? sh[lane] : 0.0;
        #pragma unroll
        for (int o = 16; o; o >>= 1) v += __shfl_down_sync(0xffffffffu, v, o);
        if (lane == 0) atomicAdd(slot, v);
    }
    __syncthreads();
}

// ---------------------------------------------------------------------------
__global__ __launch_bounds__(256, 5)
void fused_kernel(const float* __restrict__ pred_rotmat,
                  const float* __restrict__ pred_camera,
                  const float* __restrict__ pred_joints,
                  const float* __restrict__ pred_vertices,
                  const float* __restrict__ pred_betas,
                  const float* __restrict__ gt_rotmat,
                  const float* __restrict__ gt_shape,
                  const float* __restrict__ gt_kp2d,
                  const float* __restrict__ gt_kp3d,
                  const float* __restrict__ gt_vertices,
                  const int*   __restrict__ has_smpl,
                  int B, int V, int batchBlocks,
                  unsigned long long magic,
                  float* __restrict__ out)
{
    __shared__ double sh[32];
    __shared__ float smask[2048];
    const unsigned FM = 0xffffffffu;
    const int per_batch = V * 3;
    const int ntot = B * per_batch;
    const int n4 = ntot / 4;

    if (blockIdx.x >= batchBlocks) {
        // ================= vertex L1 + pose L2 (HBM-bound) =================
        const int vblocks = gridDim.x - batchBlocks;
        const int vbid = blockIdx.x - batchBlocks;
        const float4* pv4 = reinterpret_cast<const float4*>(pred_vertices);
        const float4* gv4 = reinterpret_cast<const float4*>(gt_vertices);

        // mask table in shared
        for (int i = threadIdx.x; i < 2048; i += blockDim.x)
            smask[i] = (i < B && __ldg(has_smpl + i) > 0) ? 1.0f : 0.0f;
        __syncthreads();

        const int stride = vblocks * blockDim.x;
        int base = vbid * blockDim.x + threadIdx.x;
        float lshape = 0.0f;

        // main unrolled loop: 8 independent 16B loads in flight per thread
        int i = base;
        for (; i + 3 * stride < n4; i += 4 * stride) {
            int i0 = i, i1 = i + stride, i2 = i + 2 * stride, i3 = i + 3 * stride;
            float4 a0 = __ldg(pv4 + i0);
            float4 a1 = __ldg(pv4 + i1);
            float4 a2 = __ldg(pv4 + i2);
            float4 a3 = __ldg(pv4 + i3);
            float4 c0 = __ldg(gv4 + i0);
            float4 c1 = __ldg(gv4 + i1);
            float4 c2 = __ldg(gv4 + i2);
            float4 c3 = __ldg(gv4 + i3);
            int idx[4] = {i0, i1, i2, i3};
            float4 aa[4] = {a0, a1, a2, a3};
            float4 cc[4] = {c0, c1, c2, c3};
            #pragma unroll
            for (int u = 0; u < 4; u++) {
                int e = idx[u] * 4;
                unsigned int b0 = (unsigned int)(((unsigned long long)(unsigned int)e * magic) >> 40);
                int r = e - (int)b0 * per_batch;
                float d0 = fabsf(aa[u].x - cc[u].x);
                float d1 = fabsf(aa[u].y - cc[u].y);
                float d2 = fabsf(aa[u].z - cc[u].z);
                float d3 = fabsf(aa[u].w - cc[u].w);
                if (r + 3 < per_batch) {
                    float m = (b0 < 2048u) ? smask[b0]
                              : ((__ldg(has_smpl + b0) > 0) ? 1.0f : 0.0f);
                    lshape += m * (d0 + d1 + d2 + d3);
                } else {
                    float d[4] = {d0, d1, d2, d3};
                    #pragma unroll
                    for (int k = 0; k < 4; k++) {
                        unsigned int bb = (unsigned int)(((unsigned long long)(unsigned int)(e + k) * magic) >> 40);
                        float m = (bb < 2048u) ? smask[bb]
                                  : ((__ldg(has_smpl + bb) > 0) ? 1.0f : 0.0f);
                        lshape += m * d[k];
                    }
                }
            }
        }
        for (; i < n4; i += stride) {
            float4 a = __ldg(pv4 + i);
            float4 c = __ldg(gv4 + i);
            int e = i * 4;
            unsigned int b0 = (unsigned int)(((unsigned long long)(unsigned int)e * magic) >> 40);
            int r = e - (int)b0 * per_batch;
            float d0 = fabsf(a.x - c.x), d1 = fabsf(a.y - c.y);
            float d2 = fabsf(a.z - c.z), d3 = fabsf(a.w - c.w);
            if (r + 3 < per_batch) {
                float m = (b0 < 2048u) ? smask[b0]
                          : ((__ldg(has_smpl + b0) > 0) ? 1.0f : 0.0f);
                lshape += m * (d0 + d1 + d2 + d3);
            } else {
                float d[4] = {d0, d1, d2, d3};
                #pragma unroll
                for (int k = 0; k < 4; k++) {
                    unsigned int bb = (unsigned int)(((unsigned long long)(unsigned int)(e + k) * magic) >> 40);
                    float m = (bb < 2048u) ? smask[bb]
                              : ((__ldg(has_smpl + bb) > 0) ? 1.0f : 0.0f);
                    lshape += m * d[k];
                }
            }
        }
        if (vbid == 0 && threadIdx.x == 0) {
            for (int e = n4 * 4; e < ntot; ++e) {
                int bb = e / per_batch;
                float m = (__ldg(has_smpl + bb) > 0) ? 1.0f : 0.0f;
                lshape += m * fabsf(__ldg(pred_vertices + e) - __ldg(gt_vertices + e));
            }
        }

        // pose loss: 216 floats/batch -> 54 float4, no boundary crossing
        float lpose = 0.0f;
        {
            const float4* pr4 = reinterpret_cast<const float4*>(pred_rotmat);
            const float4* gr4 = reinterpret_cast<const float4*>(gt_rotmat);
            int n4p = B * 54;
            for (int j = base; j < n4p; j += stride) {
                int b0 = j / 54;     // constant-divisor: compiler magic
                float m = smask[b0 & 2047];
                float4 a = __ldg(pr4 + j);
                float4 b = __ldg(gr4 + j);
                float d0 = a.x - b.x, d1 = a.y - b.y, d2 = a.z - b.z, d3 = a.w - b.w;
                lpose += m * (d0*d0 + d1*d1 + d2*d2 + d3*d3);
            }
        }

        block_reduce_add(lshape, &g_state.acc[0], sh);
        block_reduce_add(lpose,  &g_state.acc[1], sh);
    } else {
        // ================= per-batch losses (warp per batch) =================
        int gw   = (blockIdx.x * blockDim.x + threadIdx.x) >> 5;
        int lane = threadIdx.x & 31;

        if (gw < B) {
            const int b = gw;
            const bool act = (lane < 24);

            float px = 0.f, py = 0.f, pz = 0.f;
            float gx = 0.f, gy = 0.f, gz = 0.f, c3 = 0.f;
            float g2x = 0.f, g2y = 0.f, c2 = 0.f;
            if (act) {
                const float* pj = pred_joints + ((size_t)b * 24 + lane) * 3;
                px = __ldg(pj + 0); py = __ldg(pj + 1); pz = __ldg(pj + 2);
                const float* gk = gt_kp3d + ((size_t)b * 24 + lane) * 4;
                gx = __ldg(gk + 0); gy = __ldg(gk + 1); gz = __ldg(gk + 2); c3 = __ldg(gk + 3);
                const float* g2 = gt_kp2d + ((size_t)b * 24 + lane) * 3;
                g2x = __ldg(g2 + 0); g2y = __ldg(g2 + 1); c2 = __ldg(g2 + 2);
            }
            float cam0 = __ldg(pred_camera + b * 3 + 0);
            float cam1 = __ldg(pred_camera + b * 3 + 1);
            float cam2 = __ldg(pred_camera + b * 3 + 2);

            // ---- kp2d ----
            float s2 = 0.f;
            {
                float depth = __fdividef(2.0f * F_LEN, EPSF + cam0 * IMG);
                if (act) {
                    float invz = __fdividef(1.0f, pz + depth);
                    float kx = (F_LEN * (px + cam1) * invz + IMG * 0.5f) * (1.0f / IMG);
                    float ky = (F_LEN * (py + cam2) * invz + IMG * 0.5f) * (1.0f / IMG);
                    s2 = c2 * (fabsf(kx - g2x * (1.0f / IMG)) +
                               fabsf(ky - g2y * (1.0f / IMG)));
                }
            }

            // ---- kp3d ----
            float ppx = 0.5f * (__shfl_sync(FM, px, 2) + __shfl_sync(FM, px, 3));
            float ppy = 0.5f * (__shfl_sync(FM, py, 2) + __shfl_sync(FM, py, 3));
            float ppz = 0.5f * (__shfl_sync(FM, pz, 2) + __shfl_sync(FM, pz, 3));
            float gpx = 0.5f * (__shfl_sync(FM, gx, 2) + __shfl_sync(FM, gx, 3));
            float gpy = 0.5f * (__shfl_sync(FM, gy, 2) + __shfl_sync(FM, gy, 3));
            float gpz = 0.5f * (__shfl_sync(FM, gz, 2) + __shfl_sync(FM, gz, 3));
            float s3 = 0.f;
            if (act) {
                s3 = c3 * (fabsf((px - ppx) - (gx - gpx)) +
                           fabsf((py - ppy) - (gy - gpy)) +
                           fabsf((pz - ppz) - (gz - gpz)));
            }
            float s23 = wsum(s2 * (1.0f / 48.0f) + s3 * (1.0f / 72.0f));

            // ---- betas ----
            float m = (__ldg(has_smpl + b) > 0) ? 1.0f : 0.0f;
            float sb = 0.f;
            if (lane < 10) {
                float d = __ldg(pred_betas + b * 10 + lane) - __ldg(gt_shape + b * 10 + lane);
                sb = d * d;
            }
            sb = wsum(sb) * m;

            // ---- Procrustes ----
            const float inv24 = 1.0f / 24.0f;
            float m1x = wsum(px) * inv24, m1y = wsum(py) * inv24, m1z = wsum(pz) * inv24;
            float m2x = wsum(gx) * inv24, m2y = wsum(gy) * inv24, m2z = wsum(gz) * inv24;

            float x1x = 0.f, x1y = 0.f, x1z = 0.f, x2x = 0.f, x2y = 0.f, x2z = 0.f;
            if (act) {
                x1x = px - m1x; x1y = py - m1y; x1z = pz - m1z;
                x2x = gx - m2x; x2y = gy - m2y; x2z = gz - m2z;
            }
            float var1 = wsum(x1x * x1x + x1y * x1y + x1z * x1z);

            float K[3][3];
            K[0][0] = wsum(x1x * x2x) + EPSF; K[0][1] = wsum(x1x * x2y) + EPSF; K[0][2] = wsum(x1x * x2z) + EPSF;
            K[1][0] = wsum(x1y * x2x) + EPSF; K[1][1] = wsum(x1y * x2y) + EPSF; K[1][2] = wsum(x1y * x2z) + EPSF;
            K[2][0] = wsum(x1z * x2x) + EPSF; K[2][1] = wsum(x1z * x2y) + EPSF; K[2][2] = wsum(x1z * x2z) + EPSF;

            float A[3][3];
            #pragma unroll
            for (int r = 0; r < 3; r++)
                #pragma unroll
                for (int c = 0; c < 3; c++)
                    A[r][c] = K[0][r] * K[0][c] + K[1][r] * K[1][c] + K[2][r] * K[2][c];

            float Vv[3][3] = {{1.f,0.f,0.f},{0.f,1.f,0.f},{0.f,0.f,1.f}};
            float nrm = A[0][0]*A[0][0] + A[1][1]*A[1][1] + A[2][2]*A[2][2];
            for (int sweep = 0; sweep < 8; ++sweep) {
                float off = A[0][1]*A[0][1] + A[0][2]*A[0][2] + A[1][2]*A[1][2];
                if (off <= 1e-14f * nrm) break;
                #pragma unroll
                for (int p = 0; p < 2; p++) {
                    #pragma unroll
                    for (int q = p + 1; q < 3; q++) {
                        float apq = A[p][q];
                        if (fabsf(apq) < 1e-30f) continue;
                        float theta = __fdividef(A[q][q] - A[p][p], 2.0f * apq);
                        float w1 = theta * theta + 1.0f;
                        float sq = w1 * rsqrtf(w1);
                        float t = __fdividef(1.0f, fabsf(theta) + sq);
                        if (theta < 0.0f) t = -t;
                        float c = rsqrtf(t * t + 1.0f);
                        float s = t * c;
                        float app = A[p][p], aqq = A[q][q];
                        A[p][p] = app - t * apq;
                        A[q][q] = aqq + t * apq;
                        A[p][q] = A[q][p] = 0.0f;
                        int k = 3 - p - q;
                        float akp = A[k][p], akq = A[k][q];
                        A[k][p] = A[p][k] = c * akp - s * akq;
                        A[k][q] = A[q][k] = s * akp + c * akq;
                        #pragma unroll
                        for (int r = 0; r < 3; r++) {
                            float vrp = Vv[r][p], vrq = Vv[r][q];
                            Vv[r][p] = c * vrp - s * vrq;
                            Vv[r][q] = s * vrp + c * vrq;
                        }
                    }
                }
            }
            float w[3] = {A[0][0], A[1][1], A[2][2]};
            #pragma unroll
            for (int i = 0; i < 2; i++) {
                int mx = i;
                #pragma unroll
                for (int j2 = 1; j2 < 3; j2++) if (j2 > i && w[j2] > w[mx]) mx = j2;
                if (mx != i) {
                    float tw = w[i]; w[i] = w[mx]; w[mx] = tw;
                    #pragma unroll
                    for (int r = 0; r < 3; r++) {
                        float tv = Vv[r][i]; Vv[r][i] = Vv[r][mx]; Vv[r][mx] = tv;
                    }
                }
            }

            float detK = K[0][0]*(K[1][1]*K[2][2] - K[1][2]*K[2][1])
                       - K[0][1]*(K[1][0]*K[2][2] - K[1][2]*K[2][0])
                       + K[0][2]*(K[1][0]*K[2][1] - K[1][1]*K[2][0]);
            float sgn = (detK > 0.f) ? 1.f : ((detK < 0.f) ? -1.f : 0.f);
            float z[3] = {1.f, 1.f, sgn};

            float R[3][3] = {{0,0,0},{0,0,0},{0,0,0}};
            #pragma unroll
            for (int i = 0; i < 3; i++) {
                float kv[3];
                #pragma unroll
                for (int r = 0; r < 3; r++)
                    kv[r] = K[r][0]*Vv[0][i] + K[r][1]*Vv[1][i] + K[r][2]*Vv[2][i];
                float f = z[i] * rsqrtf(fmaxf(w[i], 1e-30f));
                #pragma unroll
                for (int r = 0; r < 3; r++)
                    #pragma unroll
                    for (int c = 0; c < 3; c++)
                        R[r][c] += f * Vv[r][i] * kv[c];
            }
            float trRK = 0.f;
            #pragma unroll
            for (int r = 0; r < 3; r++)
                #pragma unroll
                for (int c = 0; c < 3; c++) trRK += R[r][c] * K[c][r];
            float scale = __fdividef(trRK, var1);

            float tx = m2x - scale * (R[0][0]*m1x + R[0][1]*m1y + R[0][2]*m1z);
            float ty = m2y - scale * (R[1][0]*m1x + R[1][1]*m1y + R[1][2]*m1z);
            float tz = m2z - scale * (R[2][0]*m1x + R[2][1]*m1y + R[2][2]*m1z);

            float err = 0.f;
            if (act) {
                float hx = scale * (R[0][0]*px + R[0][1]*py + R[0][2]*pz) + tx - gx;
                float hy = scale * (R[1][0]*px + R[1][1]*py + R[1][2]*pz) + ty - gy;
                float hz = scale * (R[2][0]*px + R[2][1]*py + R[2][2]*pz) + tz - gz;
                float hsq = hx*hx + hy*hy + hz*hz;
                err = (hsq > 0.f) ? hsq * rsqrtf(hsq) : 0.f;
            }
            err = wsum(err);

            if (lane == 0) {
                atomicAdd(&g_state.acc[4], (double)s23);
                atomicAdd(&g_state.acc[2], (double)sb);
                atomicAdd(&g_state.acc[3], (double)m);
                atomicAdd(&g_state.acc[6], (double)err);
            }
        }
        __syncthreads();
    }

    // ================= finalize: last block to arrive =================
    __threadfence();
    if (threadIdx.x == 0) {
        unsigned old = atomicInc(&g_state.done, gridDim.x - 1); // wraps to 0
        if (old == gridDim.x - 1) {
            __threadfence();
            volatile double* a = g_state.acc;
            double nv         = a[3];
            double loss_shape = a[0] / (nv * (double)V * 3.0 + EPSD);
            double loss_pose  = a[1] / (nv * 216.0 + EPSD);
            double loss_betas = a[2] / (nv * 10.0 + EPSD);
            double l23 = 4.0 * a[4] / (double)B;
            double pa  = a[6] / ((double)B * 24.0);
            out[0] = (float)(l23 + loss_shape + loss_pose + 0.01*loss_betas + pa);
            // self-reset for next graph replay
            #pragma unroll
            for (int k = 0; k < 7; k++) g_state.acc[k] = 0.0;
        }
    }
}

// ---------------------------------------------------------------------------
extern "C" void kernel_launch(void* const* d_in, const int* in_sizes, int n_in,
                              void* d_out, int out_size)
{
    const float* pred_rotmat   = (const float*)d_in[0];
    const float* pred_camera   = (const float*)d_in[1];
    const float* pred_joints   = (const float*)d_in[2];
    const float* pred_vertices = (const float*)d_in[3];
    const float* pred_betas    = (const float*)d_in[4];
    const float* gt_rotmat     = (const float*)d_in[5];
    const float* gt_shape      = (const float*)d_in[6];
    const float* gt_kp2d       = (const float*)d_in[7];
    const float* gt_kp3d       = (const float*)d_in[8];
    const float* gt_vertices   = (const float*)d_in[9];
    const int*   has_smpl      = (const int*)d_in[10];

    int B = in_sizes[1] / 3;
    int ntot = in_sizes[3];
    int V = ntot / (B * 3);
    int per_batch = V * 3;

    // exact unsigned division by per_batch via magic multiply (e*d < 2^40)
    unsigned long long magic = ((1ULL << 40) / (unsigned long long)per_batch) + 1ULL;

    int batchBlocks = (B * 32 + 255) / 256;     // 64 for B=512
    int grid = 148 * 5;                          // one full wave at 5 blocks/SM
    if (grid <= batchBlocks) grid = batchBlocks + 148;

    fused_kernel<<<grid, 256>>>(pred_rotmat, pred_camera, pred_joints,
                                pred_vertices, pred_betas, gt_rotmat,
                                gt_shape, gt_kp2d, gt_kp3d, gt_vertices,
                                has_smpl, B, V, batchBlocks, magic,
                                (float*)d_out);
}